// round 1
// baseline (speedup 1.0000x reference)
#include <cuda_runtime.h>
#include <math.h>

// ============================================================================
// GAT 2-layer forward, exact-math O(n log n) reformulation.
//
// softmax_j( LeakyReLU(s_i + d_j) ) @ V  is computed via:
//   sort d descending -> prefix tables of e^{d-dmax} * v  and e^{0.2(d-dmax)} * v
//   per row: binary search split m_i, combine two prefix reads.
// Prefix sums accumulated in fp64, stored fp32.
// ============================================================================

#define NB 4
#define NN 4096
#define EPSN 1e-5f

template<int L> struct LP {
  static constexpr int CIN  = (L == 0) ? 64 : 128;
  static constexpr int H    = (L == 0) ? 4 : 1;
  static constexpr int K    = (L == 0) ? 32 : 64;
  static constexpr int COUT = H * K;
  static constexpr int BH   = NB * H;
  static constexpr int TILE = (L == 0) ? 32 : 16;
};

// ---------------- scratch (device globals; no allocation allowed) ----------
__device__ float g_mu0[NB * 64],  g_rs0[NB * 64];
__device__ float g_mu1[NB * 128], g_rs1[NB * 128];
__device__ float g_w0p[NB * 64 * 128], g_t0[NB * 128];
__device__ float g_w1p[NB * 128 * 64], g_t1[NB * 64];
__device__ float g_feat0[16 * NN * 32];
__device__ float g_feat1[4 * NN * 64];
__device__ float g_ssrc0[16 * NN], g_sdst0[16 * NN];
__device__ float g_ssrc1[4 * NN],  g_sdst1[4 * NN];
__device__ float g_sortd0[16 * NN];
__device__ int   g_perm0[16 * NN];
__device__ float g_sortd1[4 * NN];
__device__ int   g_perm1[4 * NN];
__device__ float g_featS0[16 * NN * 32];
__device__ float g_featS1[4 * NN * 64];
__device__ float g_wP0[16 * NN], g_wQ0[16 * NN];
__device__ float g_wP1[4 * NN],  g_wQ1[4 * NN];
__device__ float g_pref0[(size_t)16 * 2 * (NN + 1) * 33];
__device__ float g_pref1[(size_t)4  * 2 * (NN + 1) * 65];
__device__ float g_cat[(size_t)NB * NN * 128];

// ---------------- instance-norm statistics (per b,c over N) ----------------
template<int L>
__global__ void stats_kernel(const float* __restrict__ xext) {
  constexpr int C = LP<L>::CIN;
  const float* x = (L == 0) ? xext : g_cat;
  float* mu = (L == 0) ? g_mu0 : g_mu1;
  float* rs = (L == 0) ? g_rs0 : g_rs1;
  int bc = blockIdx.x;
  int b = bc / C, c = bc % C;
  const float* p = x + (size_t)b * NN * C + c;
  double s = 0.0, s2 = 0.0;
  for (int n = threadIdx.x; n < NN; n += 256) {
    double v = (double)p[(size_t)n * C];
    s += v; s2 += v * v;
  }
  __shared__ double sh[256], sh2[256];
  sh[threadIdx.x] = s; sh2[threadIdx.x] = s2;
  __syncthreads();
  for (int off = 128; off > 0; off >>= 1) {
    if (threadIdx.x < off) {
      sh[threadIdx.x]  += sh[threadIdx.x + off];
      sh2[threadIdx.x] += sh2[threadIdx.x + off];
    }
    __syncthreads();
  }
  if (threadIdx.x == 0) {
    double mean = sh[0] / NN;
    double var  = sh2[0] / NN - mean * mean;
    mu[bc] = (float)mean;
    rs[bc] = (float)(1.0 / sqrt(var + (double)EPSN));
  }
}

// ---------------- fold instance-norm into GEMM weights ---------------------
template<int L>
__global__ void fold_kernel(const float* __restrict__ w) {
  constexpr int CIN = LP<L>::CIN, K = LP<L>::K, COUT = LP<L>::COUT;
  const float* mu = (L == 0) ? g_mu0 : g_mu1;
  const float* rs = (L == 0) ? g_rs0 : g_rs1;
  float* wp = (L == 0) ? g_w0p : g_w1p;
  float* tv = (L == 0) ? g_t0 : g_t1;
  int tid = blockIdx.x * blockDim.x + threadIdx.x;
  if (tid >= NB * COUT) return;
  int b = tid / COUT, col = tid % COUT;
  int h = col / K, k = col % K;
  float acc = 0.f;
  for (int c = 0; c < CIN; ++c) {
    float wv  = w[((size_t)h * CIN + c) * K + k];
    float wpv = wv * rs[b * CIN + c];
    wp[((size_t)b * CIN + c) * COUT + col] = wpv;
    acc += mu[b * CIN + c] * wpv;
  }
  tv[tid] = acc;
}

// ---------------- GEMM: feat[b,h,n,k] = (x-mu)/sd @ w  (folded) ------------
template<int L>
__global__ void gemm_kernel(const float* __restrict__ xext) {
  constexpr int CIN = LP<L>::CIN, H = LP<L>::H, K = LP<L>::K;
  constexpr int COUT = LP<L>::COUT, TILE = LP<L>::TILE;
  const float* x  = (L == 0) ? xext : g_cat;
  const float* wp = (L == 0) ? g_w0p : g_w1p;
  const float* tv = (L == 0) ? g_t0 : g_t1;
  float* feat = (L == 0) ? g_feat0 : g_feat1;
  __shared__ float ws[CIN * COUT];
  __shared__ float xs[TILE * CIN];
  int b = blockIdx.x, rt = blockIdx.y;
  for (int i = threadIdx.x; i < CIN * COUT; i += COUT)
    ws[i] = wp[(size_t)b * CIN * COUT + i];
  const float* xr = x + ((size_t)b * NN + (size_t)rt * TILE) * CIN;
  for (int i = threadIdx.x; i < TILE * CIN; i += COUT) xs[i] = xr[i];
  __syncthreads();
  int col = threadIdx.x;
  float tvv = tv[b * COUT + col];
  int h = col / K, k = col % K;
  float* fo = feat + (((size_t)b * H + h) * NN + (size_t)rt * TILE) * K + k;
  #pragma unroll
  for (int r0 = 0; r0 < TILE; r0 += 16) {
    float acc[16];
    #pragma unroll
    for (int r = 0; r < 16; ++r) acc[r] = -tvv;
    for (int c = 0; c < CIN; ++c) {
      float wv = ws[c * COUT + col];
      #pragma unroll
      for (int r = 0; r < 16; ++r) acc[r] += xs[(r0 + r) * CIN + c] * wv;
    }
    #pragma unroll
    for (int r = 0; r < 16; ++r) fo[(size_t)(r0 + r) * K] = acc[r];
  }
}

// ---------------- s_src / s_dst = feat . a ---------------------------------
template<int L>
__global__ void s_kernel(const float* __restrict__ a_src,
                         const float* __restrict__ a_dst) {
  constexpr int K = LP<L>::K, H = LP<L>::H, BH = LP<L>::BH;
  const float* feat = (L == 0) ? g_feat0 : g_feat1;
  float* ssrc = (L == 0) ? g_ssrc0 : g_ssrc1;
  float* sdst = (L == 0) ? g_sdst0 : g_sdst1;
  int idx = blockIdx.x * blockDim.x + threadIdx.x;
  if (idx >= BH * NN) return;
  int h = (idx / NN) % H;
  const float4* f = reinterpret_cast<const float4*>(feat + (size_t)idx * K);
  float s1 = 0.f, s2 = 0.f;
  #pragma unroll
  for (int q = 0; q < K / 4; ++q) {
    float4 v = f[q];
    const float* as = a_src + h * K + 4 * q;
    const float* ad = a_dst + h * K + 4 * q;
    s1 += v.x * as[0] + v.y * as[1] + v.z * as[2] + v.w * as[3];
    s2 += v.x * ad[0] + v.y * ad[1] + v.z * ad[2] + v.w * ad[3];
  }
  ssrc[idx] = s1;
  sdst[idx] = s2;
}

// ---------------- bitonic sort of d (descending) per bh --------------------
template<int L>
__global__ void sort_kernel() {
  const float* sdstA = (L == 0) ? g_sdst0 : g_sdst1;
  float* sortd = (L == 0) ? g_sortd0 : g_sortd1;
  int*   perm  = (L == 0) ? g_perm0 : g_perm1;
  __shared__ float key[NN];
  __shared__ int   idx[NN];
  int bh = blockIdx.x;
  for (int i = threadIdx.x; i < NN; i += blockDim.x) {
    key[i] = sdstA[(size_t)bh * NN + i];
    idx[i] = i;
  }
  __syncthreads();
  for (int k = 2; k <= NN; k <<= 1) {
    for (int j = k >> 1; j > 0; j >>= 1) {
      for (int i = threadIdx.x; i < NN; i += blockDim.x) {
        int p = i ^ j;
        if (p > i) {
          bool up = ((i & k) == 0);
          float a = key[i], bb = key[p];
          if ((a < bb) == up) {
            key[i] = bb; key[p] = a;
            int t = idx[i]; idx[i] = idx[p]; idx[p] = t;
          }
        }
      }
      __syncthreads();
    }
  }
  for (int i = threadIdx.x; i < NN; i += blockDim.x) {
    sortd[(size_t)bh * NN + i] = key[i];
    perm[(size_t)bh * NN + i]  = idx[i];
  }
}

// ---------------- permute V into sorted order + exp weights ----------------
template<int L>
__global__ void permute_kernel() {
  constexpr int K = LP<L>::K;
  const float* feat  = (L == 0) ? g_feat0 : g_feat1;
  const float* sortd = (L == 0) ? g_sortd0 : g_sortd1;
  const int*   perm  = (L == 0) ? g_perm0 : g_perm1;
  float* featS = (L == 0) ? g_featS0 : g_featS1;
  float* wP = (L == 0) ? g_wP0 : g_wP1;
  float* wQ = (L == 0) ? g_wQ0 : g_wQ1;
  int gw = (blockIdx.x * blockDim.x + threadIdx.x) >> 5;
  int lane = threadIdx.x & 31;
  int bh = gw / NN, pos = gw % NN;
  int p = perm[(size_t)bh * NN + pos];
  const float* src = feat + ((size_t)bh * NN + p) * K;
  float* dst = featS + ((size_t)bh * NN + pos) * K;
  #pragma unroll
  for (int k = lane; k < K; k += 32) dst[k] = src[k];
  if (lane == 0) {
    float dv   = sortd[(size_t)bh * NN + pos];
    float dmax = sortd[(size_t)bh * NN];
    wP[(size_t)bh * NN + pos] = expf(dv - dmax);
    wQ[(size_t)bh * NN + pos] = expf(0.2f * (dv - dmax));
  }
}

// ---------------- exclusive prefix sums (fp64 accumulate) ------------------
// chain = (bh, branch in {P,Q}, dim in [0..K]) ; dim==K is the weight column.
template<int L>
__global__ void scan_kernel() {
  constexpr int K = LP<L>::K;
  const float* featS = (L == 0) ? g_featS0 : g_featS1;
  const float* wPg = (L == 0) ? g_wP0 : g_wP1;
  const float* wQg = (L == 0) ? g_wQ0 : g_wQ1;
  float* pref = (L == 0) ? g_pref0 : g_pref1;

  int cid = blockIdx.x;
  int dim = cid % (K + 1);
  int rb = cid / (K + 1);
  int branch = rb & 1;
  int bh = rb >> 1;
  const float* w = (branch ? wQg : wPg) + (size_t)bh * NN;
  const float* v = featS + (size_t)bh * NN * K;
  float* out = pref + (((size_t)bh * 2 + branch) * (NN + 1)) * (K + 1) + dim;

  const int SEG = NN / 64;
  int t = threadIdx.x;
  double s = 0.0;
  if (dim < K) {
    for (int e = 0; e < SEG; ++e) {
      int pos = t * SEG + e;
      s += (double)w[pos] * (double)v[(size_t)pos * K + dim];
    }
  } else {
    for (int e = 0; e < SEG; ++e) s += (double)w[t * SEG + e];
  }
  __shared__ double sm[64];
  sm[t] = s;
  __syncthreads();
  if (t == 0) {
    double run = 0.0;
    for (int i = 0; i < 64; ++i) { double x = sm[i]; sm[i] = run; run += x; }
  }
  __syncthreads();
  double run = sm[t];
  if (dim < K) {
    for (int e = 0; e < SEG; ++e) {
      int pos = t * SEG + e;
      out[(size_t)pos * (K + 1)] = (float)run;
      run += (double)w[pos] * (double)v[(size_t)pos * K + dim];
    }
  } else {
    for (int e = 0; e < SEG; ++e) {
      int pos = t * SEG + e;
      out[(size_t)pos * (K + 1)] = (float)run;
      run += (double)w[pos];
    }
  }
  if (t == 63) out[(size_t)NN * (K + 1)] = (float)run;
}

// ---------------- per-row combine: binary search + prefix gather -----------
template<int L>
__global__ void rows_kernel(const float* __restrict__ bias,
                            float* __restrict__ outext) {
  constexpr int K = LP<L>::K, H = LP<L>::H;
  constexpr bool ELU = (L == 0);
  const float* ssrc  = (L == 0) ? g_ssrc0 : g_ssrc1;
  const float* sortd = (L == 0) ? g_sortd0 : g_sortd1;
  const float* pref  = (L == 0) ? g_pref0 : g_pref1;
  float* out = (L == 0) ? g_cat : outext;

  int bh = blockIdx.x;
  __shared__ float sd[NN];
  __shared__ float qt[K + 1];
  for (int i = threadIdx.x; i < NN; i += 256) sd[i] = sortd[(size_t)bh * NN + i];
  const float* prefP = pref + (size_t)bh * 2 * (NN + 1) * (K + 1);
  const float* prefQ = prefP + (size_t)(NN + 1) * (K + 1);
  if (threadIdx.x < K + 1) qt[threadIdx.x] = prefQ[(size_t)NN * (K + 1) + threadIdx.x];
  __syncthreads();

  float dmax = sd[0];
  int warp = threadIdx.x >> 5, lane = threadIdx.x & 31;
  int b = bh / H, h = bh % H;
  const int RPB = 64;  // gridDim.y == NN/RPB == 64
  int row0 = blockIdx.y * RPB;
  for (int r = row0 + warp; r < row0 + RPB; r += 8) {
    float s = ssrc[(size_t)bh * NN + r];
    float T = s + dmax;
    float alpha, beta;
    if (T > 0.f) { alpha = 1.f; beta = expf(-0.8f * T); }
    else         { alpha = expf(0.8f * T); beta = 1.f; }
    int m = 0;
    if (lane == 0) {
      float thr = -s;
      int lo = 0, hi = NN;
      while (lo < hi) {
        int mid = (lo + hi) >> 1;
        if (sd[mid] > thr) lo = mid + 1; else hi = mid;
      }
      m = lo;
    }
    m = __shfl_sync(0xffffffffu, m, 0);
    const float* pP = prefP + (size_t)m * (K + 1);
    const float* pQ = prefQ + (size_t)m * (K + 1);
    float den = alpha * pP[K] + beta * (qt[K] - pQ[K]);
    float inv = 1.f / den;
    #pragma unroll
    for (int k = lane; k < K; k += 32) {
      float num = alpha * pP[k] + beta * (qt[k] - pQ[k]);
      float v = num * inv + bias[k];
      size_t oi = ((size_t)b * NN + r) * (size_t)(H * K) + (size_t)h * K + k;
      if (ELU) out[oi] = (v > 0.f) ? v : (expf(v) - 1.f);
      else     out[oi] = v;
    }
  }
}

// ---------------- launch ----------------------------------------------------
extern "C" void kernel_launch(void* const* d_in, const int* in_sizes, int n_in,
                              void* d_out, int out_size) {
  (void)in_sizes; (void)n_in; (void)out_size;
  const float* x      = (const float*)d_in[0];
  const float* w0     = (const float*)d_in[1];
  const float* a_src0 = (const float*)d_in[2];
  const float* a_dst0 = (const float*)d_in[3];
  const float* b0     = (const float*)d_in[4];
  const float* w1     = (const float*)d_in[5];
  const float* a_src1 = (const float*)d_in[6];
  const float* a_dst1 = (const float*)d_in[7];
  const float* b1     = (const float*)d_in[8];
  float* out = (float*)d_out;

  // ---- layer 0 ----
  stats_kernel<0><<<NB * 64, 256>>>(x);
  fold_kernel<0><<<(NB * 128 + 255) / 256, 256>>>(w0);
  gemm_kernel<0><<<dim3(NB, NN / LP<0>::TILE), LP<0>::COUT>>>(x);
  s_kernel<0><<<(16 * NN) / 256, 256>>>(a_src0, a_dst0);
  sort_kernel<0><<<16, 1024>>>();
  permute_kernel<0><<<(16 * NN) / 8, 256>>>();
  scan_kernel<0><<<16 * 2 * 33, 64>>>();
  rows_kernel<0><<<dim3(16, 64), 256>>>(b0, nullptr);

  // ---- layer 1 ----
  stats_kernel<1><<<NB * 128, 256>>>(nullptr);
  fold_kernel<1><<<1, 256>>>(w1);
  gemm_kernel<1><<<dim3(NB, NN / LP<1>::TILE), LP<1>::COUT>>>(nullptr);
  s_kernel<1><<<(4 * NN) / 256, 256>>>(a_src1, a_dst1);
  sort_kernel<1><<<4, 1024>>>();
  permute_kernel<1><<<(4 * NN) / 8, 256>>>();
  scan_kernel<1><<<4 * 2 * 65, 64>>>();
  rows_kernel<1><<<dim3(4, 64), 256>>>(b1, out);
}

// round 2
// speedup vs baseline: 1.7413x; 1.7413x over previous
#include <cuda_runtime.h>
#include <math.h>
#include <cub/block/block_radix_sort.cuh>

// ============================================================================
// GAT 2-layer forward, exact-math O(n log n) reformulation.
// softmax_j(LeakyReLU(s_i + d_j)) @ V via sorted-d prefix tables:
//   sort d desc -> prefix tables of e^{d-dmax}*v (P) and e^{0.2(d-dmax)}*v (Q)
//   per row: binary search split m_i, combine alpha*P[m] + beta*(Qtot-Q[m]).
// R2: CUB radix sort, coalesced fp32 tiled scan, coalesced stats,
//     thread-parallel binary search.
// ============================================================================

#define NB 4
#define NN 4096
#define EPSN 1e-5f
#define NT 32      // scan tiles per chain
#define TS 128     // scan tile size (NT*TS == NN)
#define NSLAB 16   // stats slabs (NN/256)

template<int L> struct LP {
  static constexpr int CIN  = (L == 0) ? 64 : 128;
  static constexpr int H    = (L == 0) ? 4 : 1;
  static constexpr int K    = (L == 0) ? 32 : 64;
  static constexpr int COUT = H * K;
  static constexpr int BH   = NB * H;
  static constexpr int TILE = (L == 0) ? 32 : 16;
};

// ---------------- scratch (device globals; no allocation allowed) ----------
__device__ float g_mu0[NB * 64],  g_rs0[NB * 64];
__device__ float g_mu1[NB * 128], g_rs1[NB * 128];
__device__ float g_part0[NB * NSLAB * 64 * 2];
__device__ float g_part1[NB * NSLAB * 128 * 2];
__device__ float g_w0p[NB * 64 * 128], g_t0[NB * 128];
__device__ float g_w1p[NB * 128 * 64], g_t1[NB * 64];
__device__ float g_feat0[16 * NN * 32];
__device__ float g_feat1[4 * NN * 64];
__device__ float g_ssrc0[16 * NN], g_sdst0[16 * NN];
__device__ float g_ssrc1[4 * NN],  g_sdst1[4 * NN];
__device__ float g_sortd0[16 * NN];
__device__ int   g_perm0[16 * NN];
__device__ float g_sortd1[4 * NN];
__device__ int   g_perm1[4 * NN];
__device__ float g_featS0[16 * NN * 32];
__device__ float g_featS1[4 * NN * 64];
__device__ float g_wP0[16 * NN], g_wQ0[16 * NN];
__device__ float g_wP1[4 * NN],  g_wQ1[4 * NN];
__device__ float g_ts0[32 * NT * 33],  g_toff0[32 * NT * 33];
__device__ float g_ts1[8 * NT * 65],   g_toff1[8 * NT * 65];
__device__ float g_pref0[(size_t)16 * 2 * (NN + 1) * 33];
__device__ float g_pref1[(size_t)4  * 2 * (NN + 1) * 65];
__device__ float g_cat[(size_t)NB * NN * 128];

// ---------------- instance-norm stats: coalesced slab partials (fp32) ------
template<int L>
__global__ void stats_part_kernel(const float* __restrict__ xext) {
  constexpr int C = LP<L>::CIN;
  constexpr int RP = 256 / C;   // rows per iteration
  const float* x = (L == 0) ? xext : g_cat;
  float* part = (L == 0) ? g_part0 : g_part1;
  int b = blockIdx.x, slab = blockIdx.y;
  int c = threadIdx.x % C, rr = threadIdx.x / C;
  const float* p = x + ((size_t)b * NN + (size_t)slab * 256) * C;
  float s = 0.f, s2 = 0.f;
  for (int i = rr; i < 256; i += RP) {
    float v = p[(size_t)i * C + c];
    s += v; s2 = fmaf(v, v, s2);
  }
  __shared__ float sh[256], sh2[256];
  sh[threadIdx.x] = s; sh2[threadIdx.x] = s2;
  __syncthreads();
  if (rr == 0) {
    float S = s, S2 = s2;
    #pragma unroll
    for (int j = 1; j < RP; ++j) { S += sh[j * C + c]; S2 += sh2[j * C + c]; }
    size_t o = (((size_t)b * NSLAB + slab) * C + c) * 2;
    part[o] = S; part[o + 1] = S2;
  }
}

template<int L>
__global__ void stats_combine_kernel() {
  constexpr int C = LP<L>::CIN;
  const float* part = (L == 0) ? g_part0 : g_part1;
  float* mu = (L == 0) ? g_mu0 : g_mu1;
  float* rs = (L == 0) ? g_rs0 : g_rs1;
  int tid = blockIdx.x * blockDim.x + threadIdx.x;
  if (tid >= NB * C) return;
  int b = tid / C, c = tid % C;
  double S = 0.0, S2 = 0.0;
  for (int slab = 0; slab < NSLAB; ++slab) {
    size_t o = (((size_t)b * NSLAB + slab) * C + c) * 2;
    S += (double)part[o]; S2 += (double)part[o + 1];
  }
  double mean = S / NN;
  double var = S2 / NN - mean * mean;
  mu[tid] = (float)mean;
  rs[tid] = (float)(1.0 / sqrt(var + (double)EPSN));
}

// ---------------- fold instance-norm into GEMM weights ---------------------
template<int L>
__global__ void fold_kernel(const float* __restrict__ w) {
  constexpr int CIN = LP<L>::CIN, K = LP<L>::K, COUT = LP<L>::COUT;
  const float* mu = (L == 0) ? g_mu0 : g_mu1;
  const float* rs = (L == 0) ? g_rs0 : g_rs1;
  float* wp = (L == 0) ? g_w0p : g_w1p;
  float* tv = (L == 0) ? g_t0 : g_t1;
  int tid = blockIdx.x * blockDim.x + threadIdx.x;
  if (tid >= NB * COUT) return;
  int b = tid / COUT, col = tid % COUT;
  int h = col / K, k = col % K;
  float acc = 0.f;
  for (int c = 0; c < CIN; ++c) {
    float wv  = w[((size_t)h * CIN + c) * K + k];
    float wpv = wv * rs[b * CIN + c];
    wp[((size_t)b * CIN + c) * COUT + col] = wpv;
    acc += mu[b * CIN + c] * wpv;
  }
  tv[tid] = acc;
}

// ---------------- GEMM: feat[b,h,n,k] = (x-mu)/sd @ w  (folded) ------------
template<int L>
__global__ void gemm_kernel(const float* __restrict__ xext) {
  constexpr int CIN = LP<L>::CIN, H = LP<L>::H, K = LP<L>::K;
  constexpr int COUT = LP<L>::COUT, TILE = LP<L>::TILE;
  const float* x  = (L == 0) ? xext : g_cat;
  const float* wp = (L == 0) ? g_w0p : g_w1p;
  const float* tv = (L == 0) ? g_t0 : g_t1;
  float* feat = (L == 0) ? g_feat0 : g_feat1;
  __shared__ float ws[CIN * COUT];
  __shared__ float xs[TILE * CIN];
  int b = blockIdx.x, rt = blockIdx.y;
  for (int i = threadIdx.x; i < CIN * COUT; i += COUT)
    ws[i] = wp[(size_t)b * CIN * COUT + i];
  const float* xr = x + ((size_t)b * NN + (size_t)rt * TILE) * CIN;
  for (int i = threadIdx.x; i < TILE * CIN; i += COUT) xs[i] = xr[i];
  __syncthreads();
  int col = threadIdx.x;
  float tvv = tv[b * COUT + col];
  int h = col / K, k = col % K;
  float* fo = feat + (((size_t)b * H + h) * NN + (size_t)rt * TILE) * K + k;
  #pragma unroll
  for (int r0 = 0; r0 < TILE; r0 += 16) {
    float acc[16];
    #pragma unroll
    for (int r = 0; r < 16; ++r) acc[r] = -tvv;
    for (int c = 0; c < CIN; ++c) {
      float wv = ws[c * COUT + col];
      #pragma unroll
      for (int r = 0; r < 16; ++r) acc[r] += xs[(r0 + r) * CIN + c] * wv;
    }
    #pragma unroll
    for (int r = 0; r < 16; ++r) fo[(size_t)(r0 + r) * K] = acc[r];
  }
}

// ---------------- s_src / s_dst = feat . a ---------------------------------
template<int L>
__global__ void s_kernel(const float* __restrict__ a_src,
                         const float* __restrict__ a_dst) {
  constexpr int K = LP<L>::K, H = LP<L>::H, BH = LP<L>::BH;
  const float* feat = (L == 0) ? g_feat0 : g_feat1;
  float* ssrc = (L == 0) ? g_ssrc0 : g_ssrc1;
  float* sdst = (L == 0) ? g_sdst0 : g_sdst1;
  int idx = blockIdx.x * blockDim.x + threadIdx.x;
  if (idx >= BH * NN) return;
  int h = (idx / NN) % H;
  const float4* f = reinterpret_cast<const float4*>(feat + (size_t)idx * K);
  float s1 = 0.f, s2 = 0.f;
  #pragma unroll
  for (int q = 0; q < K / 4; ++q) {
    float4 v = f[q];
    const float* as = a_src + h * K + 4 * q;
    const float* ad = a_dst + h * K + 4 * q;
    s1 += v.x * as[0] + v.y * as[1] + v.z * as[2] + v.w * as[3];
    s2 += v.x * ad[0] + v.y * ad[1] + v.z * ad[2] + v.w * ad[3];
  }
  ssrc[idx] = s1;
  sdst[idx] = s2;
}

// ---------------- radix sort of d (descending) per bh, via CUB -------------
template<int L>
__global__ void sort_kernel() {
  constexpr int BT = 256, IPT = NN / BT;  // 16 items per thread
  const float* sdstA = (L == 0) ? g_sdst0 : g_sdst1;
  float* sortd = (L == 0) ? g_sortd0 : g_sortd1;
  int*   perm  = (L == 0) ? g_perm0 : g_perm1;
  using BRS = cub::BlockRadixSort<float, BT, IPT, int>;
  __shared__ typename BRS::TempStorage ts;
  int bh = blockIdx.x;
  const float* src = sdstA + (size_t)bh * NN;
  float keys[IPT]; int vals[IPT];
  int base = threadIdx.x * IPT;
  #pragma unroll
  for (int i = 0; i < IPT; ++i) { keys[i] = src[base + i]; vals[i] = base + i; }
  BRS(ts).SortDescending(keys, vals);
  #pragma unroll
  for (int i = 0; i < IPT; ++i) {
    sortd[(size_t)bh * NN + base + i] = keys[i];
    perm[(size_t)bh * NN + base + i]  = vals[i];
  }
}

// ---------------- permute V into sorted order + exp weights ----------------
template<int L>
__global__ void permute_kernel() {
  constexpr int K = LP<L>::K;
  const float* feat  = (L == 0) ? g_feat0 : g_feat1;
  const float* sortd = (L == 0) ? g_sortd0 : g_sortd1;
  const int*   perm  = (L == 0) ? g_perm0 : g_perm1;
  float* featS = (L == 0) ? g_featS0 : g_featS1;
  float* wP = (L == 0) ? g_wP0 : g_wP1;
  float* wQ = (L == 0) ? g_wQ0 : g_wQ1;
  int gw = (blockIdx.x * blockDim.x + threadIdx.x) >> 5;
  int lane = threadIdx.x & 31;
  int bh = gw / NN, pos = gw % NN;
  int p = perm[(size_t)bh * NN + pos];
  const float* src = feat + ((size_t)bh * NN + p) * K;
  float* dst = featS + ((size_t)bh * NN + pos) * K;
  #pragma unroll
  for (int k = lane; k < K; k += 32) dst[k] = src[k];
  if (lane == 0) {
    float dv   = sortd[(size_t)bh * NN + pos];
    float dmax = sortd[(size_t)bh * NN];
    wP[(size_t)bh * NN + pos] = expf(dv - dmax);
    wQ[(size_t)bh * NN + pos] = expf(0.2f * (dv - dmax));
  }
}

// ---------------- scan pass A: per-tile sums (coalesced, fp32) -------------
template<int L>
__global__ void scanA_kernel() {
  constexpr int K = LP<L>::K;
  constexpr int R = 128 / K;
  const float* featS = (L == 0) ? g_featS0 : g_featS1;
  const float* wPg = (L == 0) ? g_wP0 : g_wP1;
  const float* wQg = (L == 0) ? g_wQ0 : g_wQ1;
  float* tsum = (L == 0) ? g_ts0 : g_ts1;
  int chain = blockIdx.x;        // chain = bh*2 + branch
  int bh = chain >> 1, branch = chain & 1;
  const float* w = (branch ? wQg : wPg) + (size_t)bh * NN;
  const float* v = featS + (size_t)bh * NN * K;
  int tile = blockIdx.y, pos0 = tile * TS;
  int k = threadIdx.x % K, r = threadIdx.x / K;
  float acc = 0.f;
  for (int i = 0; i < TS; i += R) {
    int pos = pos0 + i + r;
    acc = fmaf(w[pos], v[(size_t)pos * K + k], acc);
  }
  __shared__ float red[128];
  red[threadIdx.x] = acc;
  __syncthreads();
  if (r == 0) {
    float s = acc;
    #pragma unroll
    for (int j = 1; j < R; ++j) s += red[j * K + k];
    tsum[((size_t)chain * NT + tile) * (K + 1) + k] = s;
  }
  if (threadIdx.x < 32) {
    float wa = 0.f;
    #pragma unroll
    for (int i = 0; i < TS / 32; ++i) wa += w[pos0 + threadIdx.x + 32 * i];
    #pragma unroll
    for (int o = 16; o; o >>= 1) wa += __shfl_down_sync(0xffffffffu, wa, o);
    if (threadIdx.x == 0) tsum[((size_t)chain * NT + tile) * (K + 1) + K] = wa;
  }
}

// ---------------- scan pass B: tile offsets + totals ------------------------
template<int L>
__global__ void scanB_kernel() {
  constexpr int K = LP<L>::K;
  const float* tsum = (L == 0) ? g_ts0 : g_ts1;
  float* toff = (L == 0) ? g_toff0 : g_toff1;
  float* pref = (L == 0) ? g_pref0 : g_pref1;
  int chain = blockIdx.x, d = threadIdx.x;
  if (d > K) return;
  float run = 0.f;
  for (int t = 0; t < NT; ++t) {
    size_t idx = ((size_t)chain * NT + t) * (K + 1) + d;
    toff[idx] = run;
    run += tsum[idx];
  }
  pref[((size_t)chain * (NN + 1) + NN) * (K + 1) + d] = run;
}

// ---------------- scan pass C: tile-local exclusive scans -------------------
// Lanes = dims, so prefix-table writes are contiguous (K+1)-float bursts.
template<int L>
__global__ void scanC_kernel() {
  constexpr int K = LP<L>::K;
  const float* featS = (L == 0) ? g_featS0 : g_featS1;
  const float* wPg = (L == 0) ? g_wP0 : g_wP1;
  const float* wQg = (L == 0) ? g_wQ0 : g_wQ1;
  const float* toff = (L == 0) ? g_toff0 : g_toff1;
  float* pref = (L == 0) ? g_pref0 : g_pref1;
  __shared__ float vs[TS * K];
  __shared__ float wsm[TS];
  int chain = blockIdx.x;
  int bh = chain >> 1, branch = chain & 1;
  int tile = blockIdx.y, pos0 = tile * TS;
  const float* w = (branch ? wQg : wPg) + (size_t)bh * NN;
  const float* v = featS + (size_t)bh * NN * K;
  for (int idx = threadIdx.x; idx < TS * K; idx += 128)
    vs[idx] = v[(size_t)pos0 * K + idx];
  wsm[threadIdx.x] = w[pos0 + threadIdx.x];
  __syncthreads();
  int d = threadIdx.x;
  if (d <= K) {
    float run = toff[((size_t)chain * NT + tile) * (K + 1) + d];
    float* out = pref + ((size_t)chain * (NN + 1) + pos0) * (K + 1) + d;
    if (d < K) {
      for (int i = 0; i < TS; ++i) {
        out[(size_t)i * (K + 1)] = run;
        run = fmaf(wsm[i], vs[i * K + d], run);
      }
    } else {
      for (int i = 0; i < TS; ++i) {
        out[(size_t)i * (K + 1)] = run;
        run += wsm[i];
      }
    }
  }
}

// ---------------- per-row combine: parallel search + prefix gather ----------
template<int L>
__global__ void rows_kernel(const float* __restrict__ bias,
                            float* __restrict__ outext) {
  constexpr int K = LP<L>::K, H = LP<L>::H;
  constexpr bool ELU = (L == 0);
  constexpr int RPB = 128;
  const float* ssrc  = (L == 0) ? g_ssrc0 : g_ssrc1;
  const float* sortd = (L == 0) ? g_sortd0 : g_sortd1;
  const float* pref  = (L == 0) ? g_pref0 : g_pref1;
  float* out = (L == 0) ? g_cat : outext;

  int bh = blockIdx.x;
  __shared__ float sd[NN];
  __shared__ int   ms[RPB];
  __shared__ float al[RPB], be[RPB];
  __shared__ float qt[K + 1];
  __shared__ float bs[K];
  for (int i = threadIdx.x; i < NN; i += 256) sd[i] = sortd[(size_t)bh * NN + i];
  const float* prefP = pref + (size_t)(bh * 2) * (NN + 1) * (K + 1);
  const float* prefQ = prefP + (size_t)(NN + 1) * (K + 1);
  if (threadIdx.x < K + 1) qt[threadIdx.x] = prefQ[(size_t)NN * (K + 1) + threadIdx.x];
  if (threadIdx.x < K) bs[threadIdx.x] = bias[threadIdx.x];
  __syncthreads();

  float dmax = sd[0];
  int row0 = blockIdx.y * RPB;

  // phase 1: one search per thread
  if (threadIdx.x < RPB) {
    int r = row0 + threadIdx.x;
    float s = ssrc[(size_t)bh * NN + r];
    float T = s + dmax;
    if (T > 0.f) { al[threadIdx.x] = 1.f; be[threadIdx.x] = expf(-0.8f * T); }
    else         { al[threadIdx.x] = expf(0.8f * T); be[threadIdx.x] = 1.f; }
    float thr = -s;
    int lo = 0, hi = NN;
    while (lo < hi) {
      int mid = (lo + hi) >> 1;
      if (sd[mid] > thr) lo = mid + 1; else hi = mid;
    }
    ms[threadIdx.x] = lo;
  }
  __syncthreads();

  // phase 2: warp per row gathers the two prefix rows
  int warp = threadIdx.x >> 5, lane = threadIdx.x & 31;
  int b = bh / H, h = bh % H;
  for (int rr = warp; rr < RPB; rr += 8) {
    int r = row0 + rr;
    int m = ms[rr];
    float alpha = al[rr], beta = be[rr];
    const float* pP = prefP + (size_t)m * (K + 1);
    const float* pQ = prefQ + (size_t)m * (K + 1);
    float den = alpha * pP[K] + beta * (qt[K] - pQ[K]);
    float inv = 1.f / den;
    #pragma unroll
    for (int k = lane; k < K; k += 32) {
      float num = alpha * pP[k] + beta * (qt[k] - pQ[k]);
      float v = num * inv + bs[k];
      size_t oi = ((size_t)b * NN + r) * (size_t)(H * K) + (size_t)h * K + k;
      if (ELU) out[oi] = (v > 0.f) ? v : (expf(v) - 1.f);
      else     out[oi] = v;
    }
  }
}

// ---------------- launch ----------------------------------------------------
extern "C" void kernel_launch(void* const* d_in, const int* in_sizes, int n_in,
                              void* d_out, int out_size) {
  (void)in_sizes; (void)n_in; (void)out_size;
  const float* x      = (const float*)d_in[0];
  const float* w0     = (const float*)d_in[1];
  const float* a_src0 = (const float*)d_in[2];
  const float* a_dst0 = (const float*)d_in[3];
  const float* b0     = (const float*)d_in[4];
  const float* w1     = (const float*)d_in[5];
  const float* a_src1 = (const float*)d_in[6];
  const float* a_dst1 = (const float*)d_in[7];
  const float* b1     = (const float*)d_in[8];
  float* out = (float*)d_out;

  // ---- layer 0 ----
  stats_part_kernel<0><<<dim3(NB, NSLAB), 256>>>(x);
  stats_combine_kernel<0><<<(NB * 64 + 127) / 128, 128>>>();
  fold_kernel<0><<<(NB * 128 + 255) / 256, 256>>>(w0);
  gemm_kernel<0><<<dim3(NB, NN / LP<0>::TILE), LP<0>::COUT>>>(x);
  s_kernel<0><<<(16 * NN) / 256, 256>>>(a_src0, a_dst0);
  sort_kernel<0><<<16, 256>>>();
  permute_kernel<0><<<(16 * NN) / 8, 256>>>();
  scanA_kernel<0><<<dim3(32, NT), 128>>>();
  scanB_kernel<0><<<32, 64>>>();
  scanC_kernel<0><<<dim3(32, NT), 128>>>();
  rows_kernel<0><<<dim3(16, NN / 128), 256>>>(b0, nullptr);

  // ---- layer 1 ----
  stats_part_kernel<1><<<dim3(NB, NSLAB), 256>>>(nullptr);
  stats_combine_kernel<1><<<(NB * 128 + 127) / 128, 128>>>();
  fold_kernel<1><<<1, 256>>>(w1);
  gemm_kernel<1><<<dim3(NB, NN / LP<1>::TILE), LP<1>::COUT>>>(nullptr);
  s_kernel<1><<<(4 * NN) / 256, 256>>>(a_src1, a_dst1);
  sort_kernel<1><<<4, 256>>>();
  permute_kernel<1><<<(4 * NN) / 8, 256>>>();
  scanA_kernel<1><<<dim3(8, NT), 128>>>();
  scanB_kernel<1><<<8, 96>>>();
  scanC_kernel<1><<<dim3(8, NT), 128>>>();
  rows_kernel<1><<<dim3(4, NN / 128), 256>>>(b1, out);
}